// round 14
// baseline (speedup 1.0000x reference)
#include <cuda_runtime.h>
#include <cuda_bf16.h>
#include <cstdint>
#include <math.h>

#define B_  16384
#define I_  1280
#define H_  320
#define D_  4
#define U1_ 512
#define U2_ 256
#define U3_ 128

// ---------------- scratch (device globals; no allocation allowed) ----------
__device__ int g_perm[B_];
__device__ int g_count[D_], g_base[D_];

__device__ __nv_bfloat16 g_h  [B_ * H_];
__device__ __nv_bfloat16 g_s  [B_ * I_];
__device__ __nv_bfloat16 g_x1 [B_ * U1_];
__device__ __nv_bfloat16 g_x2 [B_ * U2_];
__device__ __nv_bfloat16 g_ebf[B_ * I_];
__device__ __nv_bfloat16 g_pw1[D_ * I_ * H_];
__device__ __nv_bfloat16 g_pw2[D_ * H_ * I_];
__device__ __nv_bfloat16 g_dw1[I_ * U1_];
__device__ __nv_bfloat16 g_dw2[U1_ * U2_];
__device__ __nv_bfloat16 g_dw3[U2_ * U3_];

__device__ __forceinline__ __nv_bfloat16* bfbuf(int id) {
    switch (id) {
        case 0: return g_h;   case 1: return g_s;   case 2: return g_x1;
        case 3: return g_x2;  case 5: return g_ebf;
        case 6: return g_pw1; case 7: return g_pw2; case 8: return g_dw1;
        case 9: return g_dw2; case 10: return g_dw3;
    }
    return nullptr;
}

// ---------------- fp32 -> bf16 conversion ----------------------------------
__device__ __forceinline__ void cvt4(const float* __restrict__ s,
                                     __nv_bfloat16* __restrict__ d, int i) {
    float4 v = *reinterpret_cast<const float4*>(s + i);
    *reinterpret_cast<__nv_bfloat162*>(d + i)     = __floats2bfloat162_rn(v.x, v.y);
    *reinterpret_cast<__nv_bfloat162*>(d + i + 2) = __floats2bfloat162_rn(v.z, v.w);
}

__global__ void f2bf(const float* __restrict__ src, int dstid, int n) {
    int i = (blockIdx.x * 256 + threadIdx.x) * 4;
    if (i >= n) return;
    cvt4(src, bfbuf(dstid), i);
}

// all 5 weight tensors in one launch; cvt4 needs segment-LOCAL index.
#define NW1 (D_ * I_ * H_)
#define NW2 (NW1 + D_ * H_ * I_)
#define NW3 (NW2 + I_ * U1_)
#define NW4 (NW3 + U1_ * U2_)
#define NW5 (NW4 + U2_ * U3_)
__global__ void f2bf_all(const float* __restrict__ s0, const float* __restrict__ s1,
                         const float* __restrict__ s2, const float* __restrict__ s3,
                         const float* __restrict__ s4) {
    int i = (blockIdx.x * 256 + threadIdx.x) * 4;
    if (i < NW1)      cvt4(s0, g_pw1, i);
    else if (i < NW2) cvt4(s1, g_pw2, i - NW1);
    else if (i < NW3) cvt4(s2, g_dw1, i - NW2);
    else if (i < NW4) cvt4(s3, g_dw2, i - NW3);
    else if (i < NW5) cvt4(s4, g_dw3, i - NW4);
}

// ---------------- fused domain binning (single block) ----------------------
__global__ __launch_bounds__(1024) void k_bin(const int* __restrict__ dom) {
    __shared__ int cnt[D_], base[D_];
    const int t = threadIdx.x;
    if (t < D_) cnt[t] = 0;
    __syncthreads();
    for (int i = t; i < B_; i += 1024) {
        int d = dom[i]; d = d < 0 ? 0 : (d > D_ - 1 ? D_ - 1 : d);
        atomicAdd(&cnt[d], 1);
    }
    __syncthreads();
    if (t == 0) {
        int s = 0;
        for (int d = 0; d < D_; d++) {
            base[d] = s; g_base[d] = s; g_count[d] = cnt[d]; s += cnt[d];
        }
    }
    __syncthreads();
    if (t < D_) cnt[t] = 0;      // reuse as cursors
    __syncthreads();
    for (int i = t; i < B_; i += 1024) {
        int d = dom[i]; d = d < 0 ? 0 : (d > D_ - 1 ? D_ - 1 : d);
        int p = base[d] + atomicAdd(&cnt[d], 1);
        g_perm[p] = i;
    }
}

// ---------------- tensor-core / async-copy primitives ----------------------
__device__ __forceinline__ void ldsm4(uint32_t& r0, uint32_t& r1,
                                      uint32_t& r2, uint32_t& r3, uint32_t a) {
    asm volatile("ldmatrix.sync.aligned.m8n8.x4.shared.b16 {%0,%1,%2,%3}, [%4];"
                 : "=r"(r0), "=r"(r1), "=r"(r2), "=r"(r3) : "r"(a));
}
__device__ __forceinline__ void ldsm4t(uint32_t& r0, uint32_t& r1,
                                       uint32_t& r2, uint32_t& r3, uint32_t a) {
    asm volatile("ldmatrix.sync.aligned.m8n8.x4.trans.shared.b16 {%0,%1,%2,%3}, [%4];"
                 : "=r"(r0), "=r"(r1), "=r"(r2), "=r"(r3) : "r"(a));
}
__device__ __forceinline__ void mma_bf16(float* c,
                                         uint32_t a0, uint32_t a1, uint32_t a2, uint32_t a3,
                                         uint32_t b0, uint32_t b1) {
    asm volatile("mma.sync.aligned.m16n8k16.row.col.f32.bf16.bf16.f32 "
                 "{%0,%1,%2,%3}, {%4,%5,%6,%7}, {%8,%9}, {%0,%1,%2,%3};"
                 : "+f"(c[0]), "+f"(c[1]), "+f"(c[2]), "+f"(c[3])
                 : "r"(a0), "r"(a1), "r"(a2), "r"(a3), "r"(b0), "r"(b1));
}
__device__ __forceinline__ void cp16(uint32_t dst, const void* src) {
    asm volatile("cp.async.cg.shared.global [%0], [%1], 16;"
                 :: "r"(dst), "l"(src));
}
__device__ __forceinline__ void cp_commit() {
    asm volatile("cp.async.commit_group;");
}
template<int N>
__device__ __forceinline__ void cp_wait() {
    asm volatile("cp.async.wait_group %0;" :: "n"(N));
}

// ---------------- bf16 tensor-core GEMM (cp.async 3-stage) ------------------
// Block tile TM x TN x 32, 256 threads = 8 warps (4x2); warp tile (TM/4)x(TN/2).
// A rows beyond the segment are CLAMPED (not zero-filled): garbage accumulators
// only for rows whose epilogue stores are guarded off -> memory-safe.
// Inner loop: ks=0 LDSM hoisted before issue() so cp.async issue burst hides
// inside LDSM latency.
#define EPI_RELU  0
#define EPI_PRUNE 1
#define EPI_DOT   2
#define LDA_PAD 40
#define STG 3

template<int TM, int TN, int MINB, bool SEG, bool GATHER, int EPI>
__global__ __launch_bounds__(256, MINB)
void gemm_bf16(int aid, int lda, int wid, long wstride,
               const float* __restrict__ bias, int bstride,
               int cid, int ldc, int N, int K,
               const float* __restrict__ w4, const float* __restrict__ b4,
               float* __restrict__ outp)
{
    constexpr int LDBP = TN + 8;
    constexpr int WM   = TM / 4;          // warp m extent
    constexpr int WN   = TN / 2;          // warp n extent
    constexpr int MT   = WM / 16;
    constexpr int NP   = WN / 16;
    constexpr int NACC = WN / 8;
    constexpr int TNC  = TN / 8;
    constexpr int NB   = (4 * TN) / 256;  // B chunks per thread
    constexpr int NA   = TM / 64;         // A chunks per thread

    extern __shared__ char smem_raw[];
    __nv_bfloat16* Asm = reinterpret_cast<__nv_bfloat16*>(smem_raw);
    __nv_bfloat16* Bsm = reinterpret_cast<__nv_bfloat16*>(
        smem_raw + (size_t)STG * TM * LDA_PAD * 2);
    __shared__ float sred[(EPI == EPI_DOT) ? TM : 1];

    const int t = threadIdx.x;
    int bz = SEG ? blockIdx.z : 0;
    int segBase = 0, segCnt = B_;
    if (SEG) { segCnt = g_count[bz]; segBase = g_base[bz]; }

    const int m0 = blockIdx.y * TM;
    if (m0 >= segCnt) return;                 // uniform per block
    const int n0 = blockIdx.x * TN;

    const __nv_bfloat16* A  = bfbuf(aid);
    const __nv_bfloat16* Wp = bfbuf(wid) + (long)bz * wstride;
    const float*         bp = bias + bz * bstride;

    // ---- A staging roles: TM*4 chunks; rows clamped into the segment ----
    const int ac8 = (t & 3) * 8;
    const __nv_bfloat16* Ap[NA];
#pragma unroll
    for (int j = 0; j < NA; j++) {
        int row = j * 64 + (t >> 2);
        int rc  = m0 + row; rc = rc < segCnt ? rc : segCnt - 1;  // clamp
        int p   = segBase + rc;
        int gr  = GATHER ? g_perm[p] : p;
        Ap[j] = A + (size_t)gr * lda;
    }
    // ---- B staging roles ----
    int brow[NB], bcol[NB];
    const __nv_bfloat16* BgJ[NB];
#pragma unroll
    for (int j = 0; j < NB; j++) {
        int c = t + j * 256;
        brow[j] = c / TNC;
        bcol[j] = (c % TNC) * 8;
        BgJ[j]  = Wp + (size_t)brow[j] * N + n0 + bcol[j];
    }

    const uint32_t aBase0 = (uint32_t)__cvta_generic_to_shared(Asm);
    const uint32_t bBase0 = (uint32_t)__cvta_generic_to_shared(Bsm);
    constexpr uint32_t A_STG_B = TM * LDA_PAD * 2;   // stage stride bytes
    constexpr uint32_t B_STG_B = 32 * LDBP * 2;
    const uint32_t aDst0 = aBase0 + (((t >> 2) * LDA_PAD + ac8) << 1);
    const uint32_t aStride = (uint32_t)(64 * LDA_PAD) << 1;

    const int kIters = K / 32;

    auto issue = [&](int i) {
        int s = i % STG;
#pragma unroll
        for (int j = 0; j < NA; j++)
            cp16(aDst0 + s * A_STG_B + j * aStride, Ap[j] + i * 32 + ac8);
#pragma unroll
        for (int j = 0; j < NB; j++)
            cp16(bBase0 + s * B_STG_B + ((brow[j] * LDBP + bcol[j]) << 1),
                 BgJ[j] + (size_t)i * 32 * N);
        cp_commit();
    };

    issue(0);
    if (kIters > 1) issue(1);

    const int lane = t & 31, warp = t >> 5;
    const int wm = warp >> 1, wn = warp & 1;        // 4x2 warp grid
    const int aRowOff = lane & 15;
    const int aColOff = (lane >> 4) * 8;
    const int bRowOff = (lane & 7) + ((lane >> 3) & 1) * 8;
    const int bColOff = wn * WN + (lane >> 4) * 8;

    float acc[NA][NACC][4];
#pragma unroll
    for (int i = 0; i < NA; i++)
#pragma unroll
        for (int j = 0; j < NACC; j++)
#pragma unroll
            for (int k = 0; k < 4; k++) acc[i][j][k] = 0.f;

    for (int i = 0; i < kIters; i++) {
        if (i + 1 < kIters) cp_wait<1>(); else cp_wait<0>();
        __syncthreads();   // single barrier/iter: stage (i-1)%3 reads (done
                           // last iter) are ordered before issue overwrites it

        const int s = i % STG;
        const uint32_t bA = aBase0 + s * A_STG_B, bB = bBase0 + s * B_STG_B;

        // ---- ks=0 fragment loads FIRST (latency window covers issue burst) --
        uint32_t a0[MT][4], b0[NP][4];
#pragma unroll
        for (int mt = 0; mt < MT; mt++) {
            uint32_t addr = bA +
                (((wm * WM + mt * 16 + aRowOff) * LDA_PAD + aColOff) << 1);
            ldsm4(a0[mt][0], a0[mt][1], a0[mt][2], a0[mt][3], addr);
        }
#pragma unroll
        for (int np = 0; np < NP; np++) {
            uint32_t addr = bB + (((bRowOff) * LDBP + bColOff + np * 16) << 1);
            ldsm4t(b0[np][0], b0[np][1], b0[np][2], b0[np][3], addr);
        }

        if (i + STG - 1 < kIters) issue(i + STG - 1);

        // ---- ks=1 loads (overlap ks=0 MMA tail) ----
        uint32_t a1[MT][4], b1[NP][4];
#pragma unroll
        for (int mt = 0; mt < MT; mt++) {
            uint32_t addr = bA +
                (((wm * WM + mt * 16 + aRowOff) * LDA_PAD + 16 + aColOff) << 1);
            ldsm4(a1[mt][0], a1[mt][1], a1[mt][2], a1[mt][3], addr);
        }
#pragma unroll
        for (int np = 0; np < NP; np++) {
            uint32_t addr = bB + (((16 + bRowOff) * LDBP + bColOff + np * 16) << 1);
            ldsm4t(b1[np][0], b1[np][1], b1[np][2], b1[np][3], addr);
        }

#pragma unroll
        for (int mt = 0; mt < MT; mt++)
#pragma unroll
            for (int np = 0; np < NP; np++) {
                mma_bf16(acc[mt][np * 2],
                         a0[mt][0], a0[mt][1], a0[mt][2], a0[mt][3],
                         b0[np][0], b0[np][1]);
                mma_bf16(acc[mt][np * 2 + 1],
                         a0[mt][0], a0[mt][1], a0[mt][2], a0[mt][3],
                         b0[np][2], b0[np][3]);
            }
#pragma unroll
        for (int mt = 0; mt < MT; mt++)
#pragma unroll
            for (int np = 0; np < NP; np++) {
                mma_bf16(acc[mt][np * 2],
                         a1[mt][0], a1[mt][1], a1[mt][2], a1[mt][3],
                         b1[np][0], b1[np][1]);
                mma_bf16(acc[mt][np * 2 + 1],
                         a1[mt][0], a1[mt][1], a1[mt][2], a1[mt][3],
                         b1[np][2], b1[np][3]);
            }
    }

    const int g = lane >> 2, tig = lane & 3;

    if (EPI == EPI_DOT) {
        // ---- fused final layer: dot(relu(z), w4) + b4 -> sigmoid -> out ----
#pragma unroll
        for (int j = t; j < TM; j += 256) sred[j] = 0.f;
        __syncthreads();
        float p[NA][2];
#pragma unroll
        for (int mt = 0; mt < NA; mt++) { p[mt][0] = 0.f; p[mt][1] = 0.f; }
#pragma unroll
        for (int nt = 0; nt < NACC; nt++) {
            const int col = n0 + wn * WN + nt * 8 + tig * 2;
            const float bb0 = bp[col], bb1 = bp[col + 1];
            const float w0 = w4[col], w1 = w4[col + 1];
#pragma unroll
            for (int mt = 0; mt < NA; mt++)
#pragma unroll
                for (int hf = 0; hf < 2; hf++) {
                    float r0 = fmaxf(acc[mt][nt][hf * 2]     + bb0, 0.f);
                    float r1 = fmaxf(acc[mt][nt][hf * 2 + 1] + bb1, 0.f);
                    p[mt][hf] = fmaf(r0, w0, fmaf(r1, w1, p[mt][hf]));
                }
        }
#pragma unroll
        for (int mt = 0; mt < NA; mt++)
#pragma unroll
            for (int hf = 0; hf < 2; hf++) {
                float vsum = p[mt][hf];
                vsum += __shfl_xor_sync(0xffffffffu, vsum, 1);
                vsum += __shfl_xor_sync(0xffffffffu, vsum, 2);
                if (tig == 0)
                    atomicAdd(&sred[wm * WM + mt * 16 + g + hf * 8], vsum);
            }
        __syncthreads();
        const float vb4 = b4[0];
        for (int j = t; j < TM; j += 256) {
            int pos = m0 + j;
            outp[g_perm[pos]] = 1.f / (1.f + expf(-(sred[j] + vb4)));
        }
        return;
    }

    // ---- store epilogues ----
    __nv_bfloat16* C = bfbuf(cid);
#pragma unroll
    for (int mt = 0; mt < NA; mt++) {
#pragma unroll
        for (int nt = 0; nt < NACC; nt++) {
            const int col = n0 + wn * WN + nt * 8 + tig * 2;
            const float bb0 = bp[col], bb1 = bp[col + 1];
#pragma unroll
            for (int hf = 0; hf < 2; hf++) {
                const int rl = wm * WM + mt * 16 + g + hf * 8;
                if (m0 + rl >= segCnt) continue;
                const int pos = segBase + m0 + rl;
                float z0 = acc[mt][nt][hf * 2]     + bb0;
                float z1 = acc[mt][nt][hf * 2 + 1] + bb1;
                float r0, r1;
                if (EPI == EPI_RELU) {
                    r0 = fmaxf(z0, 0.f);
                    r1 = fmaxf(z1, 0.f);
                } else {
                    int grow = g_perm[pos];
                    __nv_bfloat162 e = *reinterpret_cast<const __nv_bfloat162*>(
                        &g_ebf[(size_t)grow * I_ + col]);
                    float w0 = 1.f / (1.f + __expf(-z0));  // sigmoid>0.5 <=> z>0
                    float w1 = 1.f / (1.f + __expf(-z1));
                    r0 = (z0 > 0.f) ? __bfloat162float(e.x) * w0 : 0.f;
                    r1 = (z1 > 0.f) ? __bfloat162float(e.y) * w1 : 0.f;
                }
                *reinterpret_cast<__nv_bfloat162*>(&C[(size_t)pos * ldc + col]) =
                    __floats2bfloat162_rn(r0, r1);
            }
        }
    }
}

// ---------------- launch ---------------------------------------------------
static inline int cdiv4_256(int n) { return (n / 4 + 255) / 256; }

#define SMEMSZ(TM, TN) (STG * ((TM) * LDA_PAD + 32 * ((TN) + 8)) * 2)
#define SMEM_64  SMEMSZ(128, 64)    // 44544
#define SMEM_128 SMEMSZ(128, 128)   // 56832

extern "C" void kernel_launch(void* const* d_in, const int* in_sizes, int n_in,
                              void* d_out, int out_size)
{
    const float* emb  = (const float*)d_in[0];
    const int*   dom  = (const int*)  d_in[1];
    const float* p_w1 = (const float*)d_in[2];
    const float* p_b1 = (const float*)d_in[3];
    const float* p_w2 = (const float*)d_in[4];
    const float* p_b2 = (const float*)d_in[5];
    const float* d_w1 = (const float*)d_in[6];
    const float* d_b1 = (const float*)d_in[7];
    const float* d_w2 = (const float*)d_in[8];
    const float* d_b2 = (const float*)d_in[9];
    const float* d_w3 = (const float*)d_in[10];
    const float* d_b3 = (const float*)d_in[11];
    const float* d_w4 = (const float*)d_in[12];
    const float* d_b4 = (const float*)d_in[13];
    float* out = (float*)d_out;

    cudaFuncSetAttribute(gemm_bf16<128, 128, 2, false, false, EPI_DOT>,
                         cudaFuncAttributeMaxDynamicSharedMemorySize, SMEM_128);

    // 1-3: binning + conversions
    k_bin<<<1, 1024>>>(dom);
    f2bf<<<cdiv4_256(B_ * I_), 256>>>(emb, 5, B_ * I_);
    f2bf_all<<<NW5 / 4 / 256, 256>>>(p_w1, p_w2, d_w1, d_w2, d_w3);

    // 4: pruner layer 1: h = relu(emb[perm] @ p_w1[d] + p_b1[d])
    gemm_bf16<128, 64, 3, true, true, EPI_RELU>
        <<<dim3(H_ / 64, B_ / 128, D_), 256, SMEM_64>>>(
            5, I_, 6, (long)I_ * H_, p_b1, H_, 0, H_, H_, I_,
            nullptr, nullptr, nullptr);

    // 5: pruner layer 2 + prune
    gemm_bf16<128, 64, 3, true, false, EPI_PRUNE>
        <<<dim3(I_ / 64, B_ / 128, D_), 256, SMEM_64>>>(
            0, H_, 7, (long)H_ * I_, p_b2, I_, 1, I_, I_, H_,
            nullptr, nullptr, nullptr);

    // 6: dnn layer 1  <- ncu -s 5 -c 1 profiles this launch
    gemm_bf16<128, 64, 3, false, false, EPI_RELU>
        <<<dim3(U1_ / 64, B_ / 128, 1), 256, SMEM_64>>>(
            1, I_, 8, 0, d_b1, 0, 2, U1_, U1_, I_,
            nullptr, nullptr, nullptr);
    // 7: dnn layer 2
    gemm_bf16<128, 64, 3, false, false, EPI_RELU>
        <<<dim3(U2_ / 64, B_ / 128, 1), 256, SMEM_64>>>(
            2, U1_, 9, 0, d_b2, 0, 3, U2_, U2_, U1_,
            nullptr, nullptr, nullptr);
    // 8: dnn layer 3 + fused final dot + sigmoid + scatter (TN=128: one x-block)
    gemm_bf16<128, 128, 2, false, false, EPI_DOT>
        <<<dim3(U3_ / 128, B_ / 128, 1), 256, SMEM_128>>>(
            3, U2_, 10, 0, d_b3, 0, 3, U3_, U3_, U2_,
            d_w4, d_b4, out);
}

// round 16
// speedup vs baseline: 1.0081x; 1.0081x over previous
#include <cuda_runtime.h>
#include <cuda_bf16.h>
#include <cstdint>
#include <math.h>

#define B_  16384
#define I_  1280
#define H_  320
#define D_  4
#define U1_ 512
#define U2_ 256
#define U3_ 128

// ---------------- scratch (device globals; no allocation allowed) ----------
__device__ int g_perm[B_];
__device__ int g_count[D_], g_base[D_];

__device__ __nv_bfloat16 g_h  [B_ * H_];
__device__ __nv_bfloat16 g_s  [B_ * I_];
__device__ __nv_bfloat16 g_x1 [B_ * U1_];
__device__ __nv_bfloat16 g_x2 [B_ * U2_];
__device__ __nv_bfloat16 g_ebf[B_ * I_];
__device__ __nv_bfloat16 g_pw1[D_ * I_ * H_];
__device__ __nv_bfloat16 g_pw2[D_ * H_ * I_];
__device__ __nv_bfloat16 g_dw1[I_ * U1_];
__device__ __nv_bfloat16 g_dw2[U1_ * U2_];
__device__ __nv_bfloat16 g_dw3[U2_ * U3_];

__device__ __forceinline__ __nv_bfloat16* bfbuf(int id) {
    switch (id) {
        case 0: return g_h;   case 1: return g_s;   case 2: return g_x1;
        case 3: return g_x2;  case 5: return g_ebf;
        case 6: return g_pw1; case 7: return g_pw2; case 8: return g_dw1;
        case 9: return g_dw2; case 10: return g_dw3;
    }
    return nullptr;
}

// ---------------- fp32 -> bf16 conversion ----------------------------------
__device__ __forceinline__ void cvt4(const float* __restrict__ s,
                                     __nv_bfloat16* __restrict__ d, int i) {
    float4 v = *reinterpret_cast<const float4*>(s + i);
    *reinterpret_cast<__nv_bfloat162*>(d + i)     = __floats2bfloat162_rn(v.x, v.y);
    *reinterpret_cast<__nv_bfloat162*>(d + i + 2) = __floats2bfloat162_rn(v.z, v.w);
}

__global__ void f2bf(const float* __restrict__ src, int dstid, int n) {
    int i = (blockIdx.x * 256 + threadIdx.x) * 4;
    if (i >= n) return;
    cvt4(src, bfbuf(dstid), i);
}

// all 5 weight tensors in one launch; cvt4 needs segment-LOCAL index.
#define NW1 (D_ * I_ * H_)
#define NW2 (NW1 + D_ * H_ * I_)
#define NW3 (NW2 + I_ * U1_)
#define NW4 (NW3 + U1_ * U2_)
#define NW5 (NW4 + U2_ * U3_)
__global__ void f2bf_all(const float* __restrict__ s0, const float* __restrict__ s1,
                         const float* __restrict__ s2, const float* __restrict__ s3,
                         const float* __restrict__ s4) {
    int i = (blockIdx.x * 256 + threadIdx.x) * 4;
    if (i < NW1)      cvt4(s0, g_pw1, i);
    else if (i < NW2) cvt4(s1, g_pw2, i - NW1);
    else if (i < NW3) cvt4(s2, g_dw1, i - NW2);
    else if (i < NW4) cvt4(s3, g_dw2, i - NW3);
    else if (i < NW5) cvt4(s4, g_dw3, i - NW4);
}

// ---------------- fused domain binning (single block) ----------------------
__global__ __launch_bounds__(1024) void k_bin(const int* __restrict__ dom) {
    __shared__ int cnt[D_], base[D_];
    const int t = threadIdx.x;
    if (t < D_) cnt[t] = 0;
    __syncthreads();
    for (int i = t; i < B_; i += 1024) {
        int d = dom[i]; d = d < 0 ? 0 : (d > D_ - 1 ? D_ - 1 : d);
        atomicAdd(&cnt[d], 1);
    }
    __syncthreads();
    if (t == 0) {
        int s = 0;
        for (int d = 0; d < D_; d++) {
            base[d] = s; g_base[d] = s; g_count[d] = cnt[d]; s += cnt[d];
        }
    }
    __syncthreads();
    if (t < D_) cnt[t] = 0;      // reuse as cursors
    __syncthreads();
    for (int i = t; i < B_; i += 1024) {
        int d = dom[i]; d = d < 0 ? 0 : (d > D_ - 1 ? D_ - 1 : d);
        int p = base[d] + atomicAdd(&cnt[d], 1);
        g_perm[p] = i;
    }
}

// ---------------- tensor-core / async-copy primitives ----------------------
__device__ __forceinline__ void ldsm4(uint32_t& r0, uint32_t& r1,
                                      uint32_t& r2, uint32_t& r3, uint32_t a) {
    asm volatile("ldmatrix.sync.aligned.m8n8.x4.shared.b16 {%0,%1,%2,%3}, [%4];"
                 : "=r"(r0), "=r"(r1), "=r"(r2), "=r"(r3) : "r"(a));
}
__device__ __forceinline__ void ldsm4t(uint32_t& r0, uint32_t& r1,
                                       uint32_t& r2, uint32_t& r3, uint32_t a) {
    asm volatile("ldmatrix.sync.aligned.m8n8.x4.trans.shared.b16 {%0,%1,%2,%3}, [%4];"
                 : "=r"(r0), "=r"(r1), "=r"(r2), "=r"(r3) : "r"(a));
}
__device__ __forceinline__ void mma_bf16(float* c,
                                         uint32_t a0, uint32_t a1, uint32_t a2, uint32_t a3,
                                         uint32_t b0, uint32_t b1) {
    asm volatile("mma.sync.aligned.m16n8k16.row.col.f32.bf16.bf16.f32 "
                 "{%0,%1,%2,%3}, {%4,%5,%6,%7}, {%8,%9}, {%0,%1,%2,%3};"
                 : "+f"(c[0]), "+f"(c[1]), "+f"(c[2]), "+f"(c[3])
                 : "r"(a0), "r"(a1), "r"(a2), "r"(a3), "r"(b0), "r"(b1));
}
// 16B async copy; pred=false -> zero-fill (ignore-src), no gmem read.
__device__ __forceinline__ void cp16(uint32_t dst, const void* src, bool pred) {
    int sz = pred ? 16 : 0;
    asm volatile("cp.async.cg.shared.global [%0], [%1], 16, %2;"
                 :: "r"(dst), "l"(src), "r"(sz));
}
__device__ __forceinline__ void cp_commit() {
    asm volatile("cp.async.commit_group;");
}
template<int N>
__device__ __forceinline__ void cp_wait() {
    asm volatile("cp.async.wait_group %0;" :: "n"(N));
}

// ---------------- bf16 tensor-core GEMM (cp.async 4-stage) ------------------
// Block tile TM x TN x 32, 256 threads = 8 warps (4x2); warp tile (TM/4)x(TN/2).
// 4-stage cp.async pipeline, 3 tiles in flight (wait_group<2> steady state),
// ONE __syncthreads per k-iter. Exact R10 loop body otherwise.
#define EPI_RELU  0
#define EPI_PRUNE 1
#define EPI_DOT   2
#define LDA_PAD 40
#define STG 4

template<int TM, int TN, int MINB, bool SEG, bool GATHER, int EPI>
__global__ __launch_bounds__(256, MINB)
void gemm_bf16(int aid, int lda, int wid, long wstride,
               const float* __restrict__ bias, int bstride,
               int cid, int ldc, int N, int K,
               const float* __restrict__ w4, const float* __restrict__ b4,
               float* __restrict__ outp)
{
    constexpr int LDBP = TN + 8;
    constexpr int WM   = TM / 4;          // warp m extent
    constexpr int WN   = TN / 2;          // warp n extent
    constexpr int MT   = WM / 16;
    constexpr int NP   = WN / 16;
    constexpr int NACC = WN / 8;
    constexpr int TNC  = TN / 8;
    constexpr int NB   = (4 * TN) / 256;  // B chunks per thread
    constexpr int NA   = TM / 64;         // A chunks per thread

    extern __shared__ char smem_raw[];
    __nv_bfloat16* Asm = reinterpret_cast<__nv_bfloat16*>(smem_raw);
    __nv_bfloat16* Bsm = reinterpret_cast<__nv_bfloat16*>(
        smem_raw + (size_t)STG * TM * LDA_PAD * 2);
    __shared__ float sred[(EPI == EPI_DOT) ? TM : 1];

    const int t = threadIdx.x;
    int bz = SEG ? blockIdx.z : 0;
    int segBase = 0, segCnt = B_;
    if (SEG) { segCnt = g_count[bz]; segBase = g_base[bz]; }

    const int m0 = blockIdx.y * TM;
    if (m0 >= segCnt) return;                 // uniform per block
    const int n0 = blockIdx.x * TN;

    const __nv_bfloat16* A  = bfbuf(aid);
    const __nv_bfloat16* Wp = bfbuf(wid) + (long)bz * wstride;
    const float*         bp = bias + bz * bstride;

    // ---- A staging roles: TM*4 chunks; thread t handles NA of them ----
    const int ac8 = (t & 3) * 8;
    const __nv_bfloat16* Ap[NA];
    bool v[NA];
#pragma unroll
    for (int j = 0; j < NA; j++) {
        int row = j * 64 + (t >> 2);
        v[j] = (m0 + row) < segCnt;
        Ap[j] = A;                       // fallback (no read when !v)
        if (v[j]) {
            int p = segBase + m0 + row;
            int gr = GATHER ? g_perm[p] : p;
            Ap[j] = A + (size_t)gr * lda;
        }
    }
    // ---- B staging roles ----
    int brow[NB], bcol[NB];
    const __nv_bfloat16* BgJ[NB];
#pragma unroll
    for (int j = 0; j < NB; j++) {
        int c = t + j * 256;
        brow[j] = c / TNC;
        bcol[j] = (c % TNC) * 8;
        BgJ[j]  = Wp + (size_t)brow[j] * N + n0 + bcol[j];
    }

    const uint32_t aBase0 = (uint32_t)__cvta_generic_to_shared(Asm);
    const uint32_t bBase0 = (uint32_t)__cvta_generic_to_shared(Bsm);
    constexpr uint32_t A_STG_B = TM * LDA_PAD * 2;   // stage stride bytes
    constexpr uint32_t B_STG_B = 32 * LDBP * 2;
    const uint32_t aDst0 = aBase0 + (((t >> 2) * LDA_PAD + ac8) << 1);
    const uint32_t aStride = (uint32_t)(64 * LDA_PAD) << 1;

    const int kIters = K / 32;

    auto issue = [&](int i) {
        int s = i % STG;
#pragma unroll
        for (int j = 0; j < NA; j++)
            cp16(aDst0 + s * A_STG_B + j * aStride, Ap[j] + i * 32 + ac8, v[j]);
#pragma unroll
        for (int j = 0; j < NB; j++)
            cp16(bBase0 + s * B_STG_B + ((brow[j] * LDBP + bcol[j]) << 1),
                 BgJ[j] + (size_t)i * 32 * N, true);
        cp_commit();
    };

    issue(0);
    issue(1);
    issue(2);              // kIters >= 8 for every layer in this net

    const int lane = t & 31, warp = t >> 5;
    const int wm = warp >> 1, wn = warp & 1;        // 4x2 warp grid
    const int aRowOff = lane & 15;
    const int aColOff = (lane >> 4) * 8;
    const int bRowOff = (lane & 7) + ((lane >> 3) & 1) * 8;
    const int bColOff = wn * WN + (lane >> 4) * 8;

    float acc[NA][NACC][4];
#pragma unroll
    for (int i = 0; i < NA; i++)
#pragma unroll
        for (int j = 0; j < NACC; j++)
#pragma unroll
            for (int k = 0; k < 4; k++) acc[i][j][k] = 0.f;

    for (int i = 0; i < kIters; i++) {
        // drain so tile i is complete; keep up to 2 younger tiles in flight
        if (i + 2 < kIters)      cp_wait<2>();
        else if (i + 1 < kIters) cp_wait<1>();
        else                     cp_wait<0>();
        __syncthreads();   // single barrier/iter: stage (i-1)%4 reads (done
                           // last iter) are ordered before issue overwrites it

        if (i + STG - 1 < kIters) issue(i + STG - 1);

        const int s = i % STG;
        const uint32_t bA = aBase0 + s * A_STG_B, bB = bBase0 + s * B_STG_B;
#pragma unroll
        for (int ks = 0; ks < 2; ks++) {
            uint32_t a[MT][4], b[NP][4];
#pragma unroll
            for (int mt = 0; mt < MT; mt++) {
                uint32_t addr = bA +
                    (((wm * WM + mt * 16 + aRowOff) * LDA_PAD + ks * 16 + aColOff) << 1);
                ldsm4(a[mt][0], a[mt][1], a[mt][2], a[mt][3], addr);
            }
#pragma unroll
            for (int np = 0; np < NP; np++) {
                uint32_t addr = bB +
                    (((ks * 16 + bRowOff) * LDBP + bColOff + np * 16) << 1);
                ldsm4t(b[np][0], b[np][1], b[np][2], b[np][3], addr);
            }
#pragma unroll
            for (int mt = 0; mt < MT; mt++)
#pragma unroll
                for (int np = 0; np < NP; np++) {
                    mma_bf16(acc[mt][np * 2],
                             a[mt][0], a[mt][1], a[mt][2], a[mt][3],
                             b[np][0], b[np][1]);
                    mma_bf16(acc[mt][np * 2 + 1],
                             a[mt][0], a[mt][1], a[mt][2], a[mt][3],
                             b[np][2], b[np][3]);
                }
        }
    }

    const int g = lane >> 2, tig = lane & 3;

    if (EPI == EPI_DOT) {
        // ---- fused final layer: dot(relu(z), w4) + b4 -> sigmoid -> out ----
#pragma unroll
        for (int j = t; j < TM; j += 256) sred[j] = 0.f;
        __syncthreads();
        float p[NA][2];
#pragma unroll
        for (int mt = 0; mt < NA; mt++) { p[mt][0] = 0.f; p[mt][1] = 0.f; }
#pragma unroll
        for (int nt = 0; nt < NACC; nt++) {
            const int col = n0 + wn * WN + nt * 8 + tig * 2;
            const float bb0 = bp[col], bb1 = bp[col + 1];
            const float w0 = w4[col], w1 = w4[col + 1];
#pragma unroll
            for (int mt = 0; mt < NA; mt++)
#pragma unroll
                for (int hf = 0; hf < 2; hf++) {
                    float r0 = fmaxf(acc[mt][nt][hf * 2]     + bb0, 0.f);
                    float r1 = fmaxf(acc[mt][nt][hf * 2 + 1] + bb1, 0.f);
                    p[mt][hf] = fmaf(r0, w0, fmaf(r1, w1, p[mt][hf]));
                }
        }
#pragma unroll
        for (int mt = 0; mt < NA; mt++)
#pragma unroll
            for (int hf = 0; hf < 2; hf++) {
                float vsum = p[mt][hf];
                vsum += __shfl_xor_sync(0xffffffffu, vsum, 1);
                vsum += __shfl_xor_sync(0xffffffffu, vsum, 2);
                if (tig == 0)
                    atomicAdd(&sred[wm * WM + mt * 16 + g + hf * 8], vsum);
            }
        __syncthreads();
        const float vb4 = b4[0];
        for (int j = t; j < TM; j += 256) {
            int pos = m0 + j;
            outp[g_perm[pos]] = 1.f / (1.f + expf(-(sred[j] + vb4)));
        }
        return;
    }

    // ---- store epilogues ----
    __nv_bfloat16* C = bfbuf(cid);
#pragma unroll
    for (int mt = 0; mt < NA; mt++) {
#pragma unroll
        for (int nt = 0; nt < NACC; nt++) {
            const int col = n0 + wn * WN + nt * 8 + tig * 2;
            const float bb0 = bp[col], bb1 = bp[col + 1];
#pragma unroll
            for (int hf = 0; hf < 2; hf++) {
                const int rl = wm * WM + mt * 16 + g + hf * 8;
                if (m0 + rl >= segCnt) continue;
                const int pos = segBase + m0 + rl;
                float z0 = acc[mt][nt][hf * 2]     + bb0;
                float z1 = acc[mt][nt][hf * 2 + 1] + bb1;
                float r0, r1;
                if (EPI == EPI_RELU) {
                    r0 = fmaxf(z0, 0.f);
                    r1 = fmaxf(z1, 0.f);
                } else {
                    int grow = g_perm[pos];
                    __nv_bfloat162 e = *reinterpret_cast<const __nv_bfloat162*>(
                        &g_ebf[(size_t)grow * I_ + col]);
                    float w0 = 1.f / (1.f + __expf(-z0));  // sigmoid>0.5 <=> z>0
                    float w1 = 1.f / (1.f + __expf(-z1));
                    r0 = (z0 > 0.f) ? __bfloat162float(e.x) * w0 : 0.f;
                    r1 = (z1 > 0.f) ? __bfloat162float(e.y) * w1 : 0.f;
                }
                *reinterpret_cast<__nv_bfloat162*>(&C[(size_t)pos * ldc + col]) =
                    __floats2bfloat162_rn(r0, r1);
            }
        }
    }
}

// ---------------- launch ---------------------------------------------------
static inline int cdiv4_256(int n) { return (n / 4 + 255) / 256; }

#define SMEMSZ(TM, TN) (STG * ((TM) * LDA_PAD + 32 * ((TN) + 8)) * 2)
#define SMEM_64  SMEMSZ(128, 64)    // 59392 (3 CTAs -> 178KB/SM)
#define SMEM_128 SMEMSZ(128, 128)   // 75776

extern "C" void kernel_launch(void* const* d_in, const int* in_sizes, int n_in,
                              void* d_out, int out_size)
{
    const float* emb  = (const float*)d_in[0];
    const int*   dom  = (const int*)  d_in[1];
    const float* p_w1 = (const float*)d_in[2];
    const float* p_b1 = (const float*)d_in[3];
    const float* p_w2 = (const float*)d_in[4];
    const float* p_b2 = (const float*)d_in[5];
    const float* d_w1 = (const float*)d_in[6];
    const float* d_b1 = (const float*)d_in[7];
    const float* d_w2 = (const float*)d_in[8];
    const float* d_b2 = (const float*)d_in[9];
    const float* d_w3 = (const float*)d_in[10];
    const float* d_b3 = (const float*)d_in[11];
    const float* d_w4 = (const float*)d_in[12];
    const float* d_b4 = (const float*)d_in[13];
    float* out = (float*)d_out;

    // dynamic smem opt-in (>48KB) for all gemm instantiations (idempotent)
    cudaFuncSetAttribute(gemm_bf16<128, 64, 3, true,  true,  EPI_RELU>,
                         cudaFuncAttributeMaxDynamicSharedMemorySize, SMEM_64);
    cudaFuncSetAttribute(gemm_bf16<128, 64, 3, true,  false, EPI_PRUNE>,
                         cudaFuncAttributeMaxDynamicSharedMemorySize, SMEM_64);
    cudaFuncSetAttribute(gemm_bf16<128, 64, 3, false, false, EPI_RELU>,
                         cudaFuncAttributeMaxDynamicSharedMemorySize, SMEM_64);
    cudaFuncSetAttribute(gemm_bf16<128, 128, 2, false, false, EPI_DOT>,
                         cudaFuncAttributeMaxDynamicSharedMemorySize, SMEM_128);

    // 1-3: binning + conversions
    k_bin<<<1, 1024>>>(dom);
    f2bf<<<cdiv4_256(B_ * I_), 256>>>(emb, 5, B_ * I_);
    f2bf_all<<<NW5 / 4 / 256, 256>>>(p_w1, p_w2, d_w1, d_w2, d_w3);

    // 4: pruner layer 1: h = relu(emb[perm] @ p_w1[d] + p_b1[d])
    gemm_bf16<128, 64, 3, true, true, EPI_RELU>
        <<<dim3(H_ / 64, B_ / 128, D_), 256, SMEM_64>>>(
            5, I_, 6, (long)I_ * H_, p_b1, H_, 0, H_, H_, I_,
            nullptr, nullptr, nullptr);

    // 5: pruner layer 2 + prune
    gemm_bf16<128, 64, 3, true, false, EPI_PRUNE>
        <<<dim3(I_ / 64, B_ / 128, D_), 256, SMEM_64>>>(
            0, H_, 7, (long)H_ * I_, p_b2, I_, 1, I_, I_, H_,
            nullptr, nullptr, nullptr);

    // 6: dnn layer 1  <- ncu -s 5 -c 1 profiles this launch
    gemm_bf16<128, 64, 3, false, false, EPI_RELU>
        <<<dim3(U1_ / 64, B_ / 128, 1), 256, SMEM_64>>>(
            1, I_, 8, 0, d_b1, 0, 2, U1_, U1_, I_,
            nullptr, nullptr, nullptr);
    // 7: dnn layer 2
    gemm_bf16<128, 64, 3, false, false, EPI_RELU>
        <<<dim3(U2_ / 64, B_ / 128, 1), 256, SMEM_64>>>(
            2, U1_, 9, 0, d_b2, 0, 3, U2_, U2_, U1_,
            nullptr, nullptr, nullptr);
    // 8: dnn layer 3 + fused final dot + sigmoid + scatter (TN=128: one x-block)
    gemm_bf16<128, 128, 2, false, false, EPI_DOT>
        <<<dim3(U3_ / 128, B_ / 128, 1), 256, SMEM_128>>>(
            3, U2_, 10, 0, d_b3, 0, 3, U3_, U3_, U2_,
            d_w4, d_b4, out);
}

// round 17
// speedup vs baseline: 1.0882x; 1.0794x over previous
#include <cuda_runtime.h>
#include <cuda_bf16.h>
#include <cstdint>
#include <math.h>

#define B_  16384
#define I_  1280
#define H_  320
#define D_  4
#define U1_ 512
#define U2_ 256
#define U3_ 128

// ---------------- scratch (device globals; no allocation allowed) ----------
__device__ int g_perm[B_];
__device__ int g_count[D_], g_base[D_];

__device__ __nv_bfloat16 g_h  [B_ * H_];
__device__ __nv_bfloat16 g_s  [B_ * I_];
__device__ __nv_bfloat16 g_x1 [B_ * U1_];
__device__ __nv_bfloat16 g_x2 [B_ * U2_];
__device__ __nv_bfloat16 g_ebf[B_ * I_];
__device__ __nv_bfloat16 g_pw1[D_ * I_ * H_];
__device__ __nv_bfloat16 g_pw2[D_ * H_ * I_];
__device__ __nv_bfloat16 g_dw1[I_ * U1_];
__device__ __nv_bfloat16 g_dw2[U1_ * U2_];
__device__ __nv_bfloat16 g_dw3[U2_ * U3_];

__device__ __forceinline__ __nv_bfloat16* bfbuf(int id) {
    switch (id) {
        case 0: return g_h;   case 1: return g_s;   case 2: return g_x1;
        case 3: return g_x2;  case 5: return g_ebf;
        case 6: return g_pw1; case 7: return g_pw2; case 8: return g_dw1;
        case 9: return g_dw2; case 10: return g_dw3;
    }
    return nullptr;
}

// ---------------- fused prep: binning + ALL fp32->bf16 conversions ----------
// One launch, 1024 threads/block. Block 0 does the counting-sort binning on
// one SM while all other blocks convert emb + weights on the rest of the chip
// (fully independent work -> concurrent instead of serial launches).
__device__ __forceinline__ void cvt4(const float* __restrict__ s,
                                     __nv_bfloat16* __restrict__ d, int i) {
    float4 v = *reinterpret_cast<const float4*>(s + i);
    *reinterpret_cast<__nv_bfloat162*>(d + i)     = __floats2bfloat162_rn(v.x, v.y);
    *reinterpret_cast<__nv_bfloat162*>(d + i + 2) = __floats2bfloat162_rn(v.z, v.w);
}

#define NEMB_BLK (B_ * I_ / 4 / 1024)          // 5120 (exact)
#define NW1 (D_ * I_ * H_)
#define NW2 (NW1 + D_ * H_ * I_)
#define NW3 (NW2 + I_ * U1_)
#define NW4 (NW3 + U1_ * U2_)
#define NW5 (NW4 + U2_ * U3_)
#define NWT_BLK (NW5 / 4 / 1024)               // 1000 (exact)
#define PREP_GRID (1 + NEMB_BLK + NWT_BLK)     // 6121

__global__ __launch_bounds__(1024)
void prep(const int* __restrict__ dom, const float* __restrict__ emb,
          const float* __restrict__ s0, const float* __restrict__ s1,
          const float* __restrict__ s2, const float* __restrict__ s3,
          const float* __restrict__ s4)
{
    const int t = threadIdx.x;
    if (blockIdx.x == 0) {
        // ---- counting-sort binning (order within a domain irrelevant:
        //      all rows of a domain share weights -> deterministic output) ----
        __shared__ int cnt[D_], base[D_];
        if (t < D_) cnt[t] = 0;
        __syncthreads();
        for (int i = t; i < B_; i += 1024) {
            int d = dom[i]; d = d < 0 ? 0 : (d > D_ - 1 ? D_ - 1 : d);
            atomicAdd(&cnt[d], 1);
        }
        __syncthreads();
        if (t == 0) {
            int s = 0;
            for (int d = 0; d < D_; d++) {
                base[d] = s; g_base[d] = s; g_count[d] = cnt[d]; s += cnt[d];
            }
        }
        __syncthreads();
        if (t < D_) cnt[t] = 0;      // reuse as cursors
        __syncthreads();
        for (int i = t; i < B_; i += 1024) {
            int d = dom[i]; d = d < 0 ? 0 : (d > D_ - 1 ? D_ - 1 : d);
            int p = base[d] + atomicAdd(&cnt[d], 1);
            g_perm[p] = i;
        }
    } else if (blockIdx.x <= NEMB_BLK) {
        // ---- emb conversion ----
        int i = ((blockIdx.x - 1) * 1024 + t) * 4;
        cvt4(emb, g_ebf, i);
    } else {
        // ---- weight conversions (segment-local indices) ----
        int i = ((blockIdx.x - 1 - NEMB_BLK) * 1024 + t) * 4;
        if (i < NW1)      cvt4(s0, g_pw1, i);
        else if (i < NW2) cvt4(s1, g_pw2, i - NW1);
        else if (i < NW3) cvt4(s2, g_dw1, i - NW2);
        else if (i < NW4) cvt4(s3, g_dw2, i - NW3);
        else              cvt4(s4, g_dw3, i - NW4);
    }
}

// ---------------- tensor-core / async-copy primitives ----------------------
__device__ __forceinline__ void ldsm4(uint32_t& r0, uint32_t& r1,
                                      uint32_t& r2, uint32_t& r3, uint32_t a) {
    asm volatile("ldmatrix.sync.aligned.m8n8.x4.shared.b16 {%0,%1,%2,%3}, [%4];"
                 : "=r"(r0), "=r"(r1), "=r"(r2), "=r"(r3) : "r"(a));
}
__device__ __forceinline__ void ldsm4t(uint32_t& r0, uint32_t& r1,
                                       uint32_t& r2, uint32_t& r3, uint32_t a) {
    asm volatile("ldmatrix.sync.aligned.m8n8.x4.trans.shared.b16 {%0,%1,%2,%3}, [%4];"
                 : "=r"(r0), "=r"(r1), "=r"(r2), "=r"(r3) : "r"(a));
}
__device__ __forceinline__ void mma_bf16(float* c,
                                         uint32_t a0, uint32_t a1, uint32_t a2, uint32_t a3,
                                         uint32_t b0, uint32_t b1) {
    asm volatile("mma.sync.aligned.m16n8k16.row.col.f32.bf16.bf16.f32 "
                 "{%0,%1,%2,%3}, {%4,%5,%6,%7}, {%8,%9}, {%0,%1,%2,%3};"
                 : "+f"(c[0]), "+f"(c[1]), "+f"(c[2]), "+f"(c[3])
                 : "r"(a0), "r"(a1), "r"(a2), "r"(a3), "r"(b0), "r"(b1));
}
// 16B async copy; pred=false -> zero-fill (ignore-src), no gmem read.
__device__ __forceinline__ void cp16(uint32_t dst, const void* src, bool pred) {
    int sz = pred ? 16 : 0;
    asm volatile("cp.async.cg.shared.global [%0], [%1], 16, %2;"
                 :: "r"(dst), "l"(src), "r"(sz));
}
__device__ __forceinline__ void cp_commit() {
    asm volatile("cp.async.commit_group;");
}
template<int N>
__device__ __forceinline__ void cp_wait() {
    asm volatile("cp.async.wait_group %0;" :: "n"(N));
}

// ---------------- bf16 tensor-core GEMM (cp.async 3-stage, R10 config) ------
// Block tile TM x TN x 32, 256 threads = 8 warps (4x2); warp tile (TM/4)x(TN/2).
#define EPI_RELU  0
#define EPI_PRUNE 1
#define EPI_DOT   2
#define LDA_PAD 40
#define STG 3

template<int TM, int TN, int MINB, bool SEG, bool GATHER, int EPI>
__global__ __launch_bounds__(256, MINB)
void gemm_bf16(int aid, int lda, int wid, long wstride,
               const float* __restrict__ bias, int bstride,
               int cid, int ldc, int N, int K,
               const float* __restrict__ w4, const float* __restrict__ b4,
               float* __restrict__ outp)
{
    constexpr int LDBP = TN + 8;
    constexpr int WM   = TM / 4;          // warp m extent
    constexpr int WN   = TN / 2;          // warp n extent
    constexpr int MT   = WM / 16;
    constexpr int NP   = WN / 16;
    constexpr int NACC = WN / 8;
    constexpr int TNC  = TN / 8;
    constexpr int NB   = (4 * TN) / 256;  // B chunks per thread
    constexpr int NA   = TM / 64;         // A chunks per thread

    extern __shared__ char smem_raw[];
    __nv_bfloat16* Asm = reinterpret_cast<__nv_bfloat16*>(smem_raw);
    __nv_bfloat16* Bsm = reinterpret_cast<__nv_bfloat16*>(
        smem_raw + (size_t)STG * TM * LDA_PAD * 2);
    __shared__ float sred[(EPI == EPI_DOT) ? TM : 1];

    const int t = threadIdx.x;
    int bz = SEG ? blockIdx.z : 0;
    int segBase = 0, segCnt = B_;
    if (SEG) { segCnt = g_count[bz]; segBase = g_base[bz]; }

    const int m0 = blockIdx.y * TM;
    if (m0 >= segCnt) return;                 // uniform per block
    const int n0 = blockIdx.x * TN;

    const __nv_bfloat16* A  = bfbuf(aid);
    const __nv_bfloat16* Wp = bfbuf(wid) + (long)bz * wstride;
    const float*         bp = bias + bz * bstride;

    // ---- A staging roles: TM*4 chunks; thread t handles NA of them ----
    const int ac8 = (t & 3) * 8;
    const __nv_bfloat16* Ap[NA];
    bool v[NA];
#pragma unroll
    for (int j = 0; j < NA; j++) {
        int row = j * 64 + (t >> 2);
        v[j] = (m0 + row) < segCnt;
        Ap[j] = A;                       // fallback (no read when !v)
        if (v[j]) {
            int p = segBase + m0 + row;
            int gr = GATHER ? g_perm[p] : p;
            Ap[j] = A + (size_t)gr * lda;
        }
    }
    // ---- B staging roles ----
    int brow[NB], bcol[NB];
    const __nv_bfloat16* BgJ[NB];
#pragma unroll
    for (int j = 0; j < NB; j++) {
        int c = t + j * 256;
        brow[j] = c / TNC;
        bcol[j] = (c % TNC) * 8;
        BgJ[j]  = Wp + (size_t)brow[j] * N + n0 + bcol[j];
    }

    const uint32_t aBase0 = (uint32_t)__cvta_generic_to_shared(Asm);
    const uint32_t bBase0 = (uint32_t)__cvta_generic_to_shared(Bsm);
    constexpr uint32_t A_STG_B = TM * LDA_PAD * 2;   // stage stride bytes
    constexpr uint32_t B_STG_B = 32 * LDBP * 2;
    const uint32_t aDst0 = aBase0 + (((t >> 2) * LDA_PAD + ac8) << 1);
    const uint32_t aStride = (uint32_t)(64 * LDA_PAD) << 1;

    const int kIters = K / 32;

    auto issue = [&](int i) {
        int s = i % STG;
#pragma unroll
        for (int j = 0; j < NA; j++)
            cp16(aDst0 + s * A_STG_B + j * aStride, Ap[j] + i * 32 + ac8, v[j]);
#pragma unroll
        for (int j = 0; j < NB; j++)
            cp16(bBase0 + s * B_STG_B + ((brow[j] * LDBP + bcol[j]) << 1),
                 BgJ[j] + (size_t)i * 32 * N, true);
        cp_commit();
    };

    issue(0);
    if (kIters > 1) issue(1);

    const int lane = t & 31, warp = t >> 5;
    const int wm = warp >> 1, wn = warp & 1;        // 4x2 warp grid
    const int aRowOff = lane & 15;
    const int aColOff = (lane >> 4) * 8;
    const int bRowOff = (lane & 7) + ((lane >> 3) & 1) * 8;
    const int bColOff = wn * WN + (lane >> 4) * 8;

    float acc[NA][NACC][4];
#pragma unroll
    for (int i = 0; i < NA; i++)
#pragma unroll
        for (int j = 0; j < NACC; j++)
#pragma unroll
            for (int k = 0; k < 4; k++) acc[i][j][k] = 0.f;

    for (int i = 0; i < kIters; i++) {
        if (i + 1 < kIters) cp_wait<1>(); else cp_wait<0>();
        __syncthreads();   // single barrier/iter: stage (i-1)%3 reads (done
                           // last iter) are ordered before issue overwrites it

        if (i + STG - 1 < kIters) issue(i + STG - 1);

        const int s = i % STG;
        const uint32_t bA = aBase0 + s * A_STG_B, bB = bBase0 + s * B_STG_B;
#pragma unroll
        for (int ks = 0; ks < 2; ks++) {
            uint32_t a[MT][4], b[NP][4];
#pragma unroll
            for (int mt = 0; mt < MT; mt++) {
                uint32_t addr = bA +
                    (((wm * WM + mt * 16 + aRowOff) * LDA_PAD + ks * 16 + aColOff) << 1);
                ldsm4(a[mt][0], a[mt][1], a[mt][2], a[mt][3], addr);
            }
#pragma unroll
            for (int np = 0; np < NP; np++) {
                uint32_t addr = bB +
                    (((ks * 16 + bRowOff) * LDBP + bColOff + np * 16) << 1);
                ldsm4t(b[np][0], b[np][1], b[np][2], b[np][3], addr);
            }
#pragma unroll
            for (int mt = 0; mt < MT; mt++)
#pragma unroll
                for (int np = 0; np < NP; np++) {
                    mma_bf16(acc[mt][np * 2],
                             a[mt][0], a[mt][1], a[mt][2], a[mt][3],
                             b[np][0], b[np][1]);
                    mma_bf16(acc[mt][np * 2 + 1],
                             a[mt][0], a[mt][1], a[mt][2], a[mt][3],
                             b[np][2], b[np][3]);
                }
        }
    }

    const int g = lane >> 2, tig = lane & 3;

    if (EPI == EPI_DOT) {
        // ---- fused final layer: dot(relu(z), w4) + b4 -> sigmoid -> out ----
#pragma unroll
        for (int j = t; j < TM; j += 256) sred[j] = 0.f;
        __syncthreads();
        float p[NA][2];
#pragma unroll
        for (int mt = 0; mt < NA; mt++) { p[mt][0] = 0.f; p[mt][1] = 0.f; }
#pragma unroll
        for (int nt = 0; nt < NACC; nt++) {
            const int col = n0 + wn * WN + nt * 8 + tig * 2;
            const float bb0 = bp[col], bb1 = bp[col + 1];
            const float w0 = w4[col], w1 = w4[col + 1];
#pragma unroll
            for (int mt = 0; mt < NA; mt++)
#pragma unroll
                for (int hf = 0; hf < 2; hf++) {
                    float r0 = fmaxf(acc[mt][nt][hf * 2]     + bb0, 0.f);
                    float r1 = fmaxf(acc[mt][nt][hf * 2 + 1] + bb1, 0.f);
                    p[mt][hf] = fmaf(r0, w0, fmaf(r1, w1, p[mt][hf]));
                }
        }
#pragma unroll
        for (int mt = 0; mt < NA; mt++)
#pragma unroll
            for (int hf = 0; hf < 2; hf++) {
                float vsum = p[mt][hf];
                vsum += __shfl_xor_sync(0xffffffffu, vsum, 1);
                vsum += __shfl_xor_sync(0xffffffffu, vsum, 2);
                if (tig == 0)
                    atomicAdd(&sred[wm * WM + mt * 16 + g + hf * 8], vsum);
            }
        __syncthreads();
        const float vb4 = b4[0];
        for (int j = t; j < TM; j += 256) {
            int pos = m0 + j;
            outp[g_perm[pos]] = 1.f / (1.f + expf(-(sred[j] + vb4)));
        }
        return;
    }

    // ---- store epilogues ----
    __nv_bfloat16* C = bfbuf(cid);
#pragma unroll
    for (int mt = 0; mt < NA; mt++) {
#pragma unroll
        for (int nt = 0; nt < NACC; nt++) {
            const int col = n0 + wn * WN + nt * 8 + tig * 2;
            const float bb0 = bp[col], bb1 = bp[col + 1];
#pragma unroll
            for (int hf = 0; hf < 2; hf++) {
                const int rl = wm * WM + mt * 16 + g + hf * 8;
                if (m0 + rl >= segCnt) continue;
                const int pos = segBase + m0 + rl;
                float z0 = acc[mt][nt][hf * 2]     + bb0;
                float z1 = acc[mt][nt][hf * 2 + 1] + bb1;
                float r0, r1;
                if (EPI == EPI_RELU) {
                    r0 = fmaxf(z0, 0.f);
                    r1 = fmaxf(z1, 0.f);
                } else {
                    int grow = g_perm[pos];
                    __nv_bfloat162 e = *reinterpret_cast<const __nv_bfloat162*>(
                        &g_ebf[(size_t)grow * I_ + col]);
                    float w0 = 1.f / (1.f + __expf(-z0));  // sigmoid>0.5 <=> z>0
                    float w1 = 1.f / (1.f + __expf(-z1));
                    r0 = (z0 > 0.f) ? __bfloat162float(e.x) * w0 : 0.f;
                    r1 = (z1 > 0.f) ? __bfloat162float(e.y) * w1 : 0.f;
                }
                *reinterpret_cast<__nv_bfloat162*>(&C[(size_t)pos * ldc + col]) =
                    __floats2bfloat162_rn(r0, r1);
            }
        }
    }
}

// ---------------- launch ---------------------------------------------------
#define SMEMSZ(TM, TN) (STG * ((TM) * LDA_PAD + 32 * ((TN) + 8)) * 2)
#define SMEM_64  SMEMSZ(128, 64)    // 44544 (<48K, 3 CTAs/SM)
#define SMEM_128 SMEMSZ(128, 128)   // 56832

extern "C" void kernel_launch(void* const* d_in, const int* in_sizes, int n_in,
                              void* d_out, int out_size)
{
    const float* emb  = (const float*)d_in[0];
    const int*   dom  = (const int*)  d_in[1];
    const float* p_w1 = (const float*)d_in[2];
    const float* p_b1 = (const float*)d_in[3];
    const float* p_w2 = (const float*)d_in[4];
    const float* p_b2 = (const float*)d_in[5];
    const float* d_w1 = (const float*)d_in[6];
    const float* d_b1 = (const float*)d_in[7];
    const float* d_w2 = (const float*)d_in[8];
    const float* d_b2 = (const float*)d_in[9];
    const float* d_w3 = (const float*)d_in[10];
    const float* d_b3 = (const float*)d_in[11];
    const float* d_w4 = (const float*)d_in[12];
    const float* d_b4 = (const float*)d_in[13];
    float* out = (float*)d_out;

    cudaFuncSetAttribute(gemm_bf16<128, 128, 2, false, false, EPI_DOT>,
                         cudaFuncAttributeMaxDynamicSharedMemorySize, SMEM_128);

    // 1: fused prep — binning (block 0) runs CONCURRENTLY with all
    //    fp32->bf16 conversions (blocks 1..6120)
    prep<<<PREP_GRID, 1024>>>(dom, emb, p_w1, p_w2, d_w1, d_w2, d_w3);

    // 2: pruner layer 1: h = relu(emb[perm] @ p_w1[d] + p_b1[d])
    gemm_bf16<128, 64, 3, true, true, EPI_RELU>
        <<<dim3(H_ / 64, B_ / 128, D_), 256, SMEM_64>>>(
            5, I_, 6, (long)I_ * H_, p_b1, H_, 0, H_, H_, I_,
            nullptr, nullptr, nullptr);

    // 3: pruner layer 2 + prune
    gemm_bf16<128, 64, 3, true, false, EPI_PRUNE>
        <<<dim3(I_ / 64, B_ / 128, D_), 256, SMEM_64>>>(
            0, H_, 7, (long)H_ * I_, p_b2, I_, 1, I_, I_, H_,
            nullptr, nullptr, nullptr);

    // 4: dnn layer 1
    gemm_bf16<128, 64, 3, false, false, EPI_RELU>
        <<<dim3(U1_ / 64, B_ / 128, 1), 256, SMEM_64>>>(
            1, I_, 8, 0, d_b1, 0, 2, U1_, U1_, I_,
            nullptr, nullptr, nullptr);
    // 5: dnn layer 2
    gemm_bf16<128, 64, 3, false, false, EPI_RELU>
        <<<dim3(U2_ / 64, B_ / 128, 1), 256, SMEM_64>>>(
            2, U1_, 9, 0, d_b2, 0, 3, U2_, U2_, U1_,
            nullptr, nullptr, nullptr);
    // 6: dnn layer 3 + fused final dot + sigmoid + scatter (TN=128: one x-block)
    gemm_bf16<128, 128, 2, false, false, EPI_DOT>
        <<<dim3(U3_ / 128, B_ / 128, 1), 256, SMEM_128>>>(
            3, U2_, 10, 0, d_b3, 0, 3, U3_, U3_, U2_,
            d_w4, d_b4, out);
}